// round 3
// baseline (speedup 1.0000x reference)
#include <cuda_runtime.h>
#include <cuda_fp16.h>
#include <cstdint>

// patch2image fold, separable 2-kernel form, fp16 intermediate.
//   T[n][r][i][q] = sum_{j=0..7, 0<=q-j<=248} x[n][r*249+(q-j)][i*8+j]
//   out[n][p][q]  = ( sum_{i: 0<=p-i<=248} T[n][p-i][i][q] ) / (cnt_p*cnt_q)
//
// K1: warp = 2 rows x 16 float4-slots; __ldcs streaming reads (keep T in L2).
//     Sliding 4-tap window per lane, halves merged via shfl_xor(1) + delay line.
//     T stored as fp16 (16.3 MB -> L2-resident).
// K2: half2 per thread, fully coalesced; T reads hit L2.

#define NPOS 62001
#define W 249
#define H 256
#define NB 16

__device__ __half g_T[(size_t)NB * W * 8 * 256];   // 16.3 MB scratch

__global__ __launch_bounds__(256)
void k1_rowscan(const float* __restrict__ x) {
    const int lane = threadIdx.x & 31;
    const int warp = threadIdx.x >> 5;
    const int u16  = lane & 15;       // float4 slot within position = i*2 + h
    const int r2   = lane >> 4;
    const int h    = u16 & 1;         // 0: j in 0..3, 1: j in 4..7

    int gw = blockIdx.x * 8 + warp;   // 0..7999
    const int seg   = gw & 3;  gw >>= 2;
    const int rpair = gw % 125;
    const int n     = gw / 125;

    const int r = rpair * 2 + r2;
    const bool rvalid = (r < W);
    const int c0 = seg * 64;          // emission window [c0, c0+64)

    const float* __restrict__ xbase =
        x + ((size_t)n * NPOS + (size_t)(rvalid ? r : 0) * W) * 64 + u16 * 4;
    __half* __restrict__ tbase =
        g_T + (((size_t)n * W + (rvalid ? r : 0)) * 8 + (u16 >> 1)) * 256;

    // A[w]: pending partial sum for output q = c + 4*h + w
    float A0 = 0.f, A1 = 0.f, A2 = 0.f, A3 = 0.f;
    // delay line (half1 finalizes q = c+4 at step c; deliver at step q)
    float D0 = 0.f, D1 = 0.f, D2 = 0.f, D3 = 0.f;

    // warmup: c = c0-7 .. c0-1 (accumulate + prime delay line, no emit)
    #pragma unroll
    for (int d = -7; d < 0; ++d) {
        const int c = c0 + d;
        float4 v = make_float4(0.f, 0.f, 0.f, 0.f);
        if (rvalid && c >= 0)                       // c <= 248 here
            v = __ldcs((const float4*)(xbase + (size_t)c * 64));
        A0 += v.x; A1 += v.y; A2 += v.z; A3 += v.w;
        const float f = A0; A0 = A1; A1 = A2; A2 = A3; A3 = 0.f;
        D3 = D2; D2 = D1; D1 = D0; D0 = f;
    }

    // main: 64 emissions in groups of 4; 2 groups unrolled -> 8 LDG in flight
    #pragma unroll 2
    for (int cb = c0; cb < c0 + 64; cb += 4) {
        float tv0, tv1, tv2, tv3;
        #pragma unroll
        for (int u = 0; u < 4; ++u) {
            const int c = cb + u;
            float4 v = make_float4(0.f, 0.f, 0.f, 0.f);
            if (rvalid && c <= W - 1)
                v = __ldcs((const float4*)(xbase + (size_t)c * 64));
            A0 += v.x; A1 += v.y; A2 += v.z; A3 += v.w;
            const float f = A0; A0 = A1; A1 = A2; A2 = A3; A3 = 0.f;
            const float send = D3;                  // f from step c-4
            D3 = D2; D2 = D1; D1 = D0; D0 = f;
            const float other = __shfl_xor_sync(0xffffffffu, send, 1);
            const float t = f + other;              // h==0: S03[c] + S47[c]
            if (u == 0) tv0 = t; else if (u == 1) tv1 = t;
            else if (u == 2) tv2 = t; else tv3 = t;
        }
        if (h == 0 && rvalid) {
            __half2 a = __floats2half2_rn(tv0, tv1);
            __half2 b = __floats2half2_rn(tv2, tv3);
            uint2 pk;
            pk.x = *(const unsigned int*)&a;
            pk.y = *(const unsigned int*)&b;
            *(uint2*)(tbase + cb) = pk;             // 8B aligned (cb % 4 == 0)
        }
    }
}

__global__ __launch_bounds__(128)
void k2_fold(float* __restrict__ out) {
    const int t = threadIdx.x;        // q pair: q0 = 2t, q1 = 2t+1
    const int p = blockIdx.x;
    const int n = blockIdx.y;

    const __half2* __restrict__ tb =
        (const __half2*)(g_T + (size_t)n * W * 8 * 256);

    float2 acc = make_float2(0.f, 0.f);
    #pragma unroll
    for (int i = 0; i < 8; ++i) {
        const int r = p - i;
        if ((unsigned)r < (unsigned)W) {
            const __half2 v = __ldcs(tb + ((size_t)r * 8 + i) * 128 + t);
            const float2 f = __half22float2(v);
            acc.x += f.x; acc.y += f.y;
        }
    }

    const int q0 = 2 * t, q1 = 2 * t + 1;
    const int ci  = (p  < 7) ? p  + 1 : (p  > W - 1 ? H - p  : 8);
    const int cj0 = (q0 < 7) ? q0 + 1 : (q0 > W - 1 ? H - q0 : 8);
    const int cj1 = (q1 < 7) ? q1 + 1 : (q1 > W - 1 ? H - q1 : 8);

    float2 o;
    o.x = acc.x * (1.0f / (float)(ci * cj0));
    o.y = acc.y * (1.0f / (float)(ci * cj1));
    *(float2*)(out + ((size_t)n * H + p) * H + q0) = o;
}

extern "C" void kernel_launch(void* const* d_in, const int* in_sizes, int n_in,
                              void* d_out, int out_size) {
    const float* x = (const float*)d_in[0];
    // d_in[1] = mask = arange(N_POS) (identity) — not needed.
    float* out = (float*)d_out;

    // K1: 8000 warps = 16 n * 125 rpairs * 4 segments
    k1_rowscan<<<1000, 256>>>(x);
    // K2: one block per (p, n), 128 threads (half2 per thread)
    dim3 g2(H, NB);
    k2_fold<<<g2, 128>>>(out);
}

// round 5
// speedup vs baseline: 1.0089x; 1.0089x over previous
#include <cuda_runtime.h>
#include <cuda_fp16.h>
#include <cstdint>

// patch2image fold, separable 2-kernel form, fp16 intermediate.
//   T[n][r][i][q] = sum_{j=0..7, 0<=q-j<=248} x[n][r*249+(q-j)][i*8+j]
//   out[n][p][q]  = ( sum_{i: 0<=p-i<=248} T[n][p-i][i][q] ) / (cnt_p*cnt_q)
//
// K1: warp = 2 rows x 16 float4-slots; plain float4 loads, unroll 4 (16 LDG.128
//     in flight — Round-2 proven config). Sliding 4-tap window per lane, halves
//     merged via shfl_xor(1) + 4-step delay line. T stored fp16 (16.3 MB).
// K2: half2 per thread, fully coalesced streaming read of T.

#define NPOS 62001
#define W 249
#define H 256
#define NB 16

__device__ __half g_T[(size_t)NB * W * 8 * 256];   // 16.3 MB scratch

__global__ __launch_bounds__(256)
void k1_rowscan(const float* __restrict__ x) {
    const int lane = threadIdx.x & 31;
    const int warp = threadIdx.x >> 5;
    const int u16  = lane & 15;       // float4 slot within position = i*2 + h
    const int r2   = lane >> 4;
    const int h    = u16 & 1;         // 0: j in 0..3, 1: j in 4..7

    int gw = blockIdx.x * 8 + warp;   // 0..7999
    const int seg   = gw & 3;  gw >>= 2;
    const int rpair = gw % 125;
    const int n     = gw / 125;

    const int r = rpair * 2 + r2;
    const bool rvalid = (r < W);
    const int c0 = seg * 64;          // emission window [c0, c0+64)

    const float* __restrict__ xbase =
        x + ((size_t)n * NPOS + (size_t)(rvalid ? r : 0) * W) * 64 + u16 * 4;
    __half* __restrict__ tbase =
        g_T + (((size_t)n * W + (rvalid ? r : 0)) * 8 + (u16 >> 1)) * 256;

    // A[w]: pending partial sum for output q = c + 4*h + w
    float A0 = 0.f, A1 = 0.f, A2 = 0.f, A3 = 0.f;
    // delay line (half1 finalizes q = c+4 at step c; deliver at step q)
    float D0 = 0.f, D1 = 0.f, D2 = 0.f, D3 = 0.f;

    // warmup: c = c0-7 .. c0-1 (accumulate + prime delay line, no emit)
    #pragma unroll
    for (int d = -7; d < 0; ++d) {
        const int c = c0 + d;
        float4 v = make_float4(0.f, 0.f, 0.f, 0.f);
        if (rvalid && c >= 0)                       // c <= 248 here
            v = *(const float4*)(xbase + (size_t)c * 64);
        A0 += v.x; A1 += v.y; A2 += v.z; A3 += v.w;
        const float f = A0; A0 = A1; A1 = A2; A2 = A3; A3 = 0.f;
        D3 = D2; D2 = D1; D1 = D0; D0 = f;
    }

    // main: 64 emissions in groups of 4; 4 groups unrolled -> 16 LDG.128 in flight
    #pragma unroll 4
    for (int cb = c0; cb < c0 + 64; cb += 4) {
        float tv0, tv1, tv2, tv3;
        #pragma unroll
        for (int u = 0; u < 4; ++u) {
            const int c = cb + u;
            float4 v = make_float4(0.f, 0.f, 0.f, 0.f);
            if (rvalid && c <= W - 1)
                v = *(const float4*)(xbase + (size_t)c * 64);
            A0 += v.x; A1 += v.y; A2 += v.z; A3 += v.w;
            const float f = A0; A0 = A1; A1 = A2; A2 = A3; A3 = 0.f;
            const float send = D3;                  // f from step c-4
            D3 = D2; D2 = D1; D1 = D0; D0 = f;
            const float other = __shfl_xor_sync(0xffffffffu, send, 1);
            const float t = f + other;              // h==0: S03[c] + S47[c]
            if (u == 0) tv0 = t; else if (u == 1) tv1 = t;
            else if (u == 2) tv2 = t; else tv3 = t;
        }
        if (h == 0 && rvalid) {
            __half2 a = __floats2half2_rn(tv0, tv1);
            __half2 b = __floats2half2_rn(tv2, tv3);
            uint2 pk;
            pk.x = *(const unsigned int*)&a;
            pk.y = *(const unsigned int*)&b;
            *(uint2*)(tbase + cb) = pk;             // 8B aligned (cb % 4 == 0)
        }
    }
}

__global__ __launch_bounds__(128)
void k2_fold(float* __restrict__ out) {
    const int t = threadIdx.x;        // q pair: q0 = 2t, q1 = 2t+1
    const int p = blockIdx.x;
    const int n = blockIdx.y;

    const __half2* __restrict__ tb =
        (const __half2*)(g_T + (size_t)n * W * 8 * 256);

    float2 acc = make_float2(0.f, 0.f);
    #pragma unroll
    for (int i = 0; i < 8; ++i) {
        const int r = p - i;
        if ((unsigned)r < (unsigned)W) {
            const __half2 v = tb[((size_t)r * 8 + i) * 128 + t];
            const float2 f = __half22float2(v);
            acc.x += f.x; acc.y += f.y;
        }
    }

    const int q0 = 2 * t, q1 = 2 * t + 1;
    const int ci  = (p  < 7) ? p  + 1 : (p  > W - 1 ? H - p  : 8);
    const int cj0 = (q0 < 7) ? q0 + 1 : (q0 > W - 1 ? H - q0 : 8);
    const int cj1 = (q1 < 7) ? q1 + 1 : (q1 > W - 1 ? H - q1 : 8);

    float2 o;
    o.x = acc.x * (1.0f / (float)(ci * cj0));
    o.y = acc.y * (1.0f / (float)(ci * cj1));
    *(float2*)(out + ((size_t)n * H + p) * H + q0) = o;
}

extern "C" void kernel_launch(void* const* d_in, const int* in_sizes, int n_in,
                              void* d_out, int out_size) {
    const float* x = (const float*)d_in[0];
    // d_in[1] = mask = arange(N_POS) (identity) — not needed.
    float* out = (float*)d_out;

    // K1: 8000 warps = 16 n * 125 rpairs * 4 segments
    k1_rowscan<<<1000, 256>>>(x);
    // K2: one block per (p, n), 128 threads (half2 per thread)
    dim3 g2(H, NB);
    k2_fold<<<g2, 128>>>(out);
}